// round 9
// baseline (speedup 1.0000x reference)
#include <cuda_runtime.h>
#include <cuda_bf16.h>

#define BATCH 8
#define NPTS  32768
#define NCH   96
#define NSAMP 1024
#define CSZ   16                // CTAs per batch (nonportable cluster)
#define NL    (NPTS / CSZ)      // 2048 points per CTA  (idx>>11 == rank)
#define T     512
#define PPT   (NL / T)          // 4 points per thread
#define NPAIR (PPT / 2)         // 2 packed pairs
#define NWARP (T / 32)          // 16 warps
#define SLOTB 24                // mailbox slot bytes: {d,x | y,z | idx,pad}

// Scratch (no device allocation allowed).
__device__ int g_idx[BATCH * NSAMP];

// ---------------- packed f32x2 helpers (per-lane IEEE rn => bit-exact) -----
typedef unsigned long long ull;
__device__ __forceinline__ ull pk(float a, float b) {
    ull r; asm("mov.b64 %0, {%1,%2};" : "=l"(r) : "f"(a), "f"(b)); return r;
}
__device__ __forceinline__ void upk(ull v, float& a, float& b) {
    asm("mov.b64 {%0,%1}, %2;" : "=f"(a), "=f"(b) : "l"(v));
}
__device__ __forceinline__ ull addx2(ull a, ull b) {
    ull r; asm("add.rn.f32x2 %0, %1, %2;" : "=l"(r) : "l"(a), "l"(b)); return r;
}
__device__ __forceinline__ ull mulx2(ull a, ull b) {
    ull r; asm("mul.rn.f32x2 %0, %1, %2;" : "=l"(r) : "l"(a), "l"(b)); return r;
}
__device__ __forceinline__ unsigned su32(const void* p) {
    unsigned r;
    asm("{.reg .u64 t; cvta.to.shared.u64 t, %1; cvt.u32.u64 %0, t;}" : "=r"(r) : "l"(p));
    return r;
}

// ---------------------------------------------------------------------------
// FPS: 16-CTA cluster per batch. Coords in registers (packed f32x2 scan);
// argmax at all levels via redux.sync (dist>=0 => u32-monotonic bits, tie ->
// min index); DSMEM push mailbox sealed by mbarrier arrive (HW-sleep wait).
// ---------------------------------------------------------------------------
__global__ void __launch_bounds__(T, 1)
fps_kernel(const float* __restrict__ xyz,
           float* __restrict__ out_xyz,
           float* __restrict__ out_idxf)
{
    extern __shared__ float smem[];
    float*    sx   = smem;                        // winner-coord lookup copies
    float*    sy   = smem + NL;
    float*    sz   = smem + 2 * NL;
    unsigned* mbar = (unsigned*)(smem + 3 * NL);  // 2 mbarriers (u64 each)
    unsigned* mb   = mbar + 4;                    // [2][CSZ] slots of 6 u32
    unsigned* swdb = mb + 2 * CSZ * 6;            // per-warp best dist bits
    unsigned* swi  = swdb + NWARP;                // per-warp best idx

    const int rank = blockIdx.x;                  // rank within cluster (grid.x==CSZ)
    const int b    = blockIdx.y;
    const int tid  = threadIdx.x;
    const int lane = tid & 31;
    const int warp = tid >> 5;
    const int base = rank * NL;
    const float* __restrict__ p = xyz + (size_t)b * NPTS * 3;

    // ---- one-time: load my 4 points -> packed registers + smem lookup copy
    ull x2[NPAIR], y2[NPAIR], z2[NPAIR];
    {
        float buf[12];
        const float4* p4 = (const float4*)(p + (size_t)(base + tid * PPT) * 3);
#pragma unroll
        for (int k = 0; k < 3; k++) ((float4*)buf)[k] = p4[k];
#pragma unroll
        for (int i = 0; i < PPT; i++) {
            sx[tid * PPT + i] = buf[3 * i];
            sy[tid * PPT + i] = buf[3 * i + 1];
            sz[tid * PPT + i] = buf[3 * i + 2];
        }
#pragma unroll
        for (int q = 0; q < NPAIR; q++) {
            x2[q] = pk(buf[6 * q + 0], buf[6 * q + 3]);
            y2[q] = pk(buf[6 * q + 1], buf[6 * q + 4]);
            z2[q] = pk(buf[6 * q + 2], buf[6 * q + 5]);
        }
    }

    const unsigned mbar_u = su32(mbar);
    const unsigned mb_u   = su32(mb);

    // ---- init mbarriers (count = CSZ producers each), then cluster barrier
    if (tid == 0) {
        asm volatile("mbarrier.init.shared.b64 [%0], %1;" :: "r"(mbar_u),      "r"((unsigned)CSZ) : "memory");
        asm volatile("mbarrier.init.shared.b64 [%0], %1;" :: "r"(mbar_u + 8u), "r"((unsigned)CSZ) : "memory");
    }
    __syncthreads();
    asm volatile("barrier.cluster.arrive.aligned;\n" ::: "memory");
    asm volatile("barrier.cluster.wait.aligned;\n"   ::: "memory");

    // Remote addresses: warp0 lane r pushes into peer r's slot[parity][rank]
    // and arrives on peer r's mbar[parity].
    unsigned rem0 = 0, rem1 = 0, remb0 = 0, remb1 = 0;
    if (warp == 0 && lane < CSZ) {
        const unsigned l0 = mb_u + (unsigned)((0 * CSZ + rank) * SLOTB);
        const unsigned l1 = mb_u + (unsigned)((1 * CSZ + rank) * SLOTB);
        asm("mapa.shared::cluster.u32 %0, %1, %2;" : "=r"(rem0)  : "r"(l0), "r"(lane));
        asm("mapa.shared::cluster.u32 %0, %1, %2;" : "=r"(rem1)  : "r"(l1), "r"(lane));
        asm("mapa.shared::cluster.u32 %0, %1, %2;" : "=r"(remb0) : "r"(mbar_u),      "r"(lane));
        asm("mapa.shared::cluster.u32 %0, %1, %2;" : "=r"(remb1) : "r"(mbar_u + 8u), "r"(lane));
    }

    float dist[PPT];
#pragma unroll
    for (int i = 0; i < PPT; i++) dist[i] = 1e10f;

    int   cur = 0;
    float cx = __ldg(p + 0), cy = __ldg(p + 1), cz = __ldg(p + 2);

    for (int s = 0; s < NSAMP; s++) {
        // Output writes on a non-critical warp (warp1), using broadcast state.
        if (rank == 0 && warp == 1 && lane == 0) {
            g_idx[b * NSAMP + s]    = cur;
            out_idxf[b * NSAMP + s] = (float)cur;
            float* o = out_xyz + ((size_t)b * NSAMP + s) * 3;
            o[0] = cx; o[1] = cy; o[2] = cz;
        }

        // ---- scan: packed (dx*dx+dy*dy)+dz*dz, rn ordering (bit-match XLA)
        const ull ncx2 = pk(-cx, -cx), ncy2 = pk(-cy, -cy), ncz2 = pk(-cz, -cz);
#pragma unroll
        for (int q = 0; q < NPAIR; q++) {
            const ull dx2 = addx2(x2[q], ncx2);
            const ull dy2 = addx2(y2[q], ncy2);
            const ull dz2 = addx2(z2[q], ncz2);
            const ull d2  = addx2(addx2(mulx2(dx2, dx2), mulx2(dy2, dy2)),
                                  mulx2(dz2, dz2));
            float d0, d1; upk(d2, d0, d1);
            dist[2 * q]     = fminf(dist[2 * q],     d0);
            dist[2 * q + 1] = fminf(dist[2 * q + 1], d1);
        }
        const float bd = fmaxf(fmaxf(dist[0], dist[1]), fmaxf(dist[2], dist[3]));
        int li = 0;
#pragma unroll
        for (int i = PPT - 1; i >= 0; i--) if (dist[i] == bd) li = i;  // first match
        const unsigned bi = (unsigned)(base + tid * PPT + li);

        // ---- warp reduce via redux (dist>=0 => bits monotone; tie -> min idx)
        const unsigned bdb  = __float_as_uint(bd);
        const unsigned wmax = __reduce_max_sync(0xffffffffu, bdb);
        const unsigned wcnd = (bdb == wmax) ? bi : 0x7fffffffu;
        const unsigned wbi  = __reduce_min_sync(0xffffffffu, wcnd);
        if (lane == 0) { swdb[warp] = wmax; swi[warp] = wbi; }
        __syncthreads();

        // ---- warp0: CTA reduce + DSMEM push + remote mbarrier arrive
        if (warp == 0) {
            const unsigned v = swdb[lane & (NWARP - 1)];
            const unsigned i = swi[lane & (NWARP - 1)];
            const unsigned cmax = __reduce_max_sync(0xffffffffu, v);
            const unsigned ccnd = (v == cmax) ? i : 0x7fffffffu;
            const unsigned ri   = __reduce_min_sync(0xffffffffu, ccnd);
            const int lj = (int)ri - base;                 // uniform -> LDS broadcast
            const unsigned wx = __float_as_uint(sx[lj]);
            const unsigned wy = __float_as_uint(sy[lj]);
            const unsigned wz = __float_as_uint(sz[lj]);
            if (lane < CSZ) {
                const unsigned rem  = (s & 1) ? rem1  : rem0;
                const unsigned remb = (s & 1) ? remb1 : remb0;
                asm volatile("st.shared::cluster.v2.b32 [%0], {%1,%2};"
                             :: "r"(rem), "r"(cmax), "r"(wx) : "memory");
                asm volatile("st.shared::cluster.v2.b32 [%0], {%1,%2};"
                             :: "r"(rem + 8u), "r"(wy), "r"(wz) : "memory");
                asm volatile("st.shared::cluster.u32 [%0], %1;"
                             :: "r"(rem + 16u), "r"(ri) : "memory");
                asm volatile("mbarrier.arrive.release.cluster.shared::cluster.b64 _, [%0];"
                             :: "r"(remb) : "memory");
            }
        }

        // ---- every warp: mbarrier wait (HW sleep), then redux over 16 CTAs
        {
            const unsigned ba = mbar_u + (unsigned)((s & 1) * 8);
            const unsigned par = (unsigned)((s >> 1) & 1);
            unsigned done;
            asm volatile("{\n\t.reg .pred p;\n\t"
                         "mbarrier.try_wait.parity.acquire.cluster.shared::cta.b64 p, [%1], %2;\n\t"
                         "selp.b32 %0, 1, 0, p;\n\t}"
                         : "=r"(done) : "r"(ba), "r"(par) : "memory");
            while (!done) {
                asm volatile("{\n\t.reg .pred p;\n\t"
                             "mbarrier.try_wait.parity.acquire.cluster.shared::cta.b64 p, [%1], %2, 0x989680;\n\t"
                             "selp.b32 %0, 1, 0, p;\n\t}"
                             : "=r"(done) : "r"(ba), "r"(par) : "memory");
            }
        }

        const unsigned slot_a = mb_u + (unsigned)(((s & 1) * CSZ + lane) * SLOTB);
        unsigned db = 0, ridx = 0x7fffffffu;
        if (lane < CSZ) {
            asm volatile("ld.shared.b32 %0, [%1];" : "=r"(db)   : "r"(slot_a)       : "memory");
            asm volatile("ld.shared.b32 %0, [%1];" : "=r"(ridx) : "r"(slot_a + 16u) : "memory");
        }
        const unsigned gmax = __reduce_max_sync(0xffffffffu, db);
        const unsigned gcnd = (lane < CSZ && db == gmax) ? ridx : 0x7fffffffu;
        const unsigned wi   = __reduce_min_sync(0xffffffffu, gcnd);
        const unsigned wslot = mb_u + (unsigned)(((s & 1) * CSZ + (wi >> 11)) * SLOTB);
        unsigned bx, by, bz;                                // uniform -> broadcast LDS
        asm volatile("ld.shared.b32 %0, [%1];" : "=r"(bx) : "r"(wslot + 4u) : "memory");
        asm volatile("ld.shared.v2.b32 {%0,%1}, [%2];"
                     : "=r"(by), "=r"(bz) : "r"(wslot + 8u) : "memory");
        cur = (int)wi;
        cx = __uint_as_float(bx); cy = __uint_as_float(by); cz = __uint_as_float(bz);
    }
}

// ---------------------------------------------------------------------------
// Feature gather: out_fea[b][c][s] = fea[b][c][g_idx[b][s]]
// ---------------------------------------------------------------------------
__global__ void gather_kernel(const float* __restrict__ fea,
                              float* __restrict__ out_fea)
{
    const int t = blockIdx.x * blockDim.x + threadIdx.x;
    if (t >= BATCH * NCH * NSAMP) return;
    const int s = t % NSAMP;
    const int c = (t / NSAMP) % NCH;
    const int b = t / (NCH * NSAMP);
    const int id = g_idx[b * NSAMP + s];
    out_fea[t] = __ldg(fea + ((size_t)b * NCH + c) * NPTS + id);
}

extern "C" void kernel_launch(void* const* d_in, const int* in_sizes, int n_in,
                              void* d_out, int out_size)
{
    const float* xyz = (const float*)d_in[0];   // (B, N, 3)
    const float* fea = (const float*)d_in[1];   // (B, C, N)

    float* out = (float*)d_out;
    // Output layout: new_xyz (B,S,3) | new_fea (B,C,S) | indices-as-float (B,S)
    float* out_xyz  = out;
    float* out_fea  = out + (size_t)BATCH * NSAMP * 3;
    float* out_idxf = out + (size_t)BATCH * NSAMP * 3 + (size_t)BATCH * NCH * NSAMP;

    const int smem_bytes = 3 * NL * 4            // coord lookup copies
                         + 16                    // 2 mbarriers
                         + 2 * CSZ * 6 * 4       // mailbox slots
                         + NWARP * 4 * 2;        // per-warp reduce scratch

    cudaFuncSetAttribute(fps_kernel, cudaFuncAttributeMaxDynamicSharedMemorySize, smem_bytes);
    cudaFuncSetAttribute(fps_kernel, cudaFuncAttributeNonPortableClusterSizeAllowed, 1);

    cudaLaunchConfig_t cfg = {};
    cfg.gridDim  = dim3(CSZ, BATCH, 1);
    cfg.blockDim = dim3(T, 1, 1);
    cfg.dynamicSmemBytes = smem_bytes;
    cudaLaunchAttribute attrs[1];
    attrs[0].id = cudaLaunchAttributeClusterDimension;
    attrs[0].val.clusterDim.x = CSZ;
    attrs[0].val.clusterDim.y = 1;
    attrs[0].val.clusterDim.z = 1;
    cfg.attrs = attrs;
    cfg.numAttrs = 1;
    cudaLaunchKernelEx(&cfg, fps_kernel, xyz, out_xyz, out_idxf);

    const int total = BATCH * NCH * NSAMP;
    gather_kernel<<<(total + 255) / 256, 256>>>(fea, out_fea);
}